// round 15
// baseline (speedup 1.0000x reference)
#include <cuda_runtime.h>
#include <math.h>
#include <stdint.h>

#define TOK 32768

// -------------------- scratch (device globals; no allocs) --------------------
__device__ float g_xz_t [(size_t)TOK*512];
__device__ float g_xz_c [(size_t)TOK*512];
__device__ float g_u_t  [(size_t)TOK*256];
__device__ float g_u_c  [(size_t)TOK*256];
__device__ float g_xd_t [(size_t)TOK*40];
__device__ float g_xd_c [(size_t)TOK*40];
__device__ float g_gy_t [(size_t)TOK*256];
__device__ float g_gy_c [(size_t)TOK*256];
__device__ float g_Pd   [4*32];

__device__ __forceinline__ float siluf(float v){ return v / (1.f + __expf(-v)); }
__device__ __forceinline__ float softplusf(float v){
  return (v > 20.f) ? v : __logf(1.f + __expf(v));
}

__device__ __forceinline__ uint32_t f2tf32(float v){
  uint32_t r; asm("cvt.rna.tf32.f32 %0, %1;" : "=r"(r) : "f"(v)); return r;
}
__device__ __forceinline__ void mma_tf32(float* d,
    uint32_t a0,uint32_t a1,uint32_t a2,uint32_t a3,uint32_t b0,uint32_t b1){
  asm volatile("mma.sync.aligned.m16n8k8.row.col.f32.tf32.tf32.f32 "
    "{%0,%1,%2,%3}, {%4,%5,%6,%7}, {%8,%9}, {%0,%1,%2,%3};"
    : "+f"(d[0]),"+f"(d[1]),"+f"(d[2]),"+f"(d[3])
    : "r"(a0),"r"(a1),"r"(a2),"r"(a3),"r"(b0),"r"(b1));
}

// -------------------- packed f32x2 helpers --------------------
__device__ __forceinline__ uint64_t pack2(float lo, float hi){
  uint64_t r; asm("mov.b64 %0, {%1,%2};" : "=l"(r) : "f"(lo), "f"(hi)); return r;
}
__device__ __forceinline__ void unpack2(uint64_t v, float& lo, float& hi){
  asm("mov.b64 {%0,%1}, %2;" : "=f"(lo), "=f"(hi) : "l"(v));
}
__device__ __forceinline__ uint64_t fma2(uint64_t a, uint64_t b, uint64_t c){
  uint64_t d; asm("fma.rn.f32x2 %0, %1, %2, %3;" : "=l"(d) : "l"(a), "l"(b), "l"(c)); return d;
}
__device__ __forceinline__ uint64_t mul2(uint64_t a, uint64_t b){
  uint64_t d; asm("mul.rn.f32x2 %0, %1, %2;" : "=l"(d) : "l"(a), "l"(b)); return d;
}

// ==================== dual tf32 GEMM: both paths in one launch (blockIdx.z) ====================
__global__ void __launch_bounds__(256)
gemm_dual_kernel(const float* __restrict__ A0, const float* __restrict__ W0, float* __restrict__ C0,
                 int asrc0, int cdst0,
                 const float* __restrict__ A1, const float* __restrict__ W1, float* __restrict__ C1,
                 int asrc1, int cdst1,
                 const float* __restrict__ Pd, int M, int N, int K)
{
  const float* A; const float* W; float* Cout; int asrc, cdst;
  if (blockIdx.z == 0) { A=A0; W=W0; Cout=C0; asrc=asrc0; cdst=cdst0; }
  else                 { A=A1; W=W1; Cout=C1; asrc=asrc1; cdst=cdst1; }

  const int RS = 136;
  __shared__ uint32_t As[2][16*RS];
  __shared__ uint32_t Ws[2][16*RS];

  int tid  = threadIdx.x;
  int row0 = blockIdx.y * 128;
  int col0 = blockIdx.x * 128;
  int lane = tid & 31, warp = tid >> 5;
  int wm = (warp & 1) * 64;
  int wn = (warp >> 1) * 32;
  int g  = lane >> 2, tig = lane & 3;

  int am  = tid >> 1;
  int akq = (tid & 1) * 8;
  int ar  = row0 + am;
  const float* arow;
  float ascale = 1.f;
  if (asrc == 0) {
    arow = A + (size_t)ar * K;
  } else if (asrc == 1) {
    int l = ar & 255; int n = ar >> 8; int c = n & 31; int b = n >> 5;
    arow = A + ((size_t)(b*8192 + l*32 + c)) * 128;
  } else {
    arow = A + (size_t)ar * 128;
    ascale = Pd[((ar >> 13) << 5) | (ar & 31)];
  }
  int wk  = tid >> 4;
  int wn8 = (tid & 15) * 8;

  float acc[4][4][4];
  #pragma unroll
  for (int i=0;i<4;i++)
    #pragma unroll
    for (int j=0;j<4;j++)
      #pragma unroll
      for (int q=0;q<4;q++) acc[i][j][q]=0.f;

  float ast[8], wst[8];
  {
    float4 a0 = *reinterpret_cast<const float4*>(arow + akq);
    float4 a1 = *reinterpret_cast<const float4*>(arow + akq + 4);
    ast[0]=a0.x; ast[1]=a0.y; ast[2]=a0.z; ast[3]=a0.w;
    ast[4]=a1.x; ast[5]=a1.y; ast[6]=a1.z; ast[7]=a1.w;
    float4 w0 = *reinterpret_cast<const float4*>(W + (size_t)wk*N + col0 + wn8);
    float4 w1 = *reinterpret_cast<const float4*>(W + (size_t)wk*N + col0 + wn8 + 4);
    wst[0]=w0.x; wst[1]=w0.y; wst[2]=w0.z; wst[3]=w0.w;
    wst[4]=w1.x; wst[5]=w1.y; wst[6]=w1.z; wst[7]=w1.w;
  }
  {
    #pragma unroll
    for (int q=0;q<8;q++) As[0][(akq+q)*RS + am] = f2tf32(ast[q]*ascale);
    #pragma unroll
    for (int q=0;q<8;q++) Ws[0][wk*RS + wn8 + q] = f2tf32(wst[q]);
  }
  __syncthreads();

  int nt = K >> 4;
  for (int t=0; t<nt; t++) {
    int cur = t & 1;
    if (t+1 < nt) {
      int k0 = (t+1) << 4;
      float4 a0 = *reinterpret_cast<const float4*>(arow + k0 + akq);
      float4 a1 = *reinterpret_cast<const float4*>(arow + k0 + akq + 4);
      ast[0]=a0.x; ast[1]=a0.y; ast[2]=a0.z; ast[3]=a0.w;
      ast[4]=a1.x; ast[5]=a1.y; ast[6]=a1.z; ast[7]=a1.w;
      float4 w0 = *reinterpret_cast<const float4*>(W + (size_t)(k0+wk)*N + col0 + wn8);
      float4 w1 = *reinterpret_cast<const float4*>(W + (size_t)(k0+wk)*N + col0 + wn8 + 4);
      wst[0]=w0.x; wst[1]=w0.y; wst[2]=w0.z; wst[3]=w0.w;
      wst[4]=w1.x; wst[5]=w1.y; wst[6]=w1.z; wst[7]=w1.w;
    }
    #pragma unroll
    for (int ks=0; ks<16; ks+=8) {
      uint32_t af[4][4], bf[4][2];
      #pragma unroll
      for (int i=0;i<4;i++){
        int mr = wm + i*16 + g;
        af[i][0] = As[cur][(ks+tig  )*RS + mr];
        af[i][1] = As[cur][(ks+tig  )*RS + mr + 8];
        af[i][2] = As[cur][(ks+tig+4)*RS + mr];
        af[i][3] = As[cur][(ks+tig+4)*RS + mr + 8];
      }
      #pragma unroll
      for (int j=0;j<4;j++){
        int nc = wn + j*8 + g;
        bf[j][0] = Ws[cur][(ks+tig  )*RS + nc];
        bf[j][1] = Ws[cur][(ks+tig+4)*RS + nc];
      }
      #pragma unroll
      for (int i=0;i<4;i++)
        #pragma unroll
        for (int j=0;j<4;j++)
          mma_tf32(acc[i][j], af[i][0],af[i][1],af[i][2],af[i][3], bf[j][0],bf[j][1]);
    }
    if (t+1 < nt) {
      int nxt = (t+1) & 1;
      #pragma unroll
      for (int q=0;q<8;q++) As[nxt][(akq+q)*RS + am] = f2tf32(ast[q]*ascale);
      #pragma unroll
      for (int q=0;q<8;q++) Ws[nxt][wk*RS + wn8 + q] = f2tf32(wst[q]);
      __syncthreads();
    }
  }

  #pragma unroll
  for (int i=0;i<4;i++){
    int r_lo = row0 + wm + i*16 + g;
    #pragma unroll
    for (int half=0; half<2; half++){
      int r = r_lo + half*8;
      float* orow;
      if (cdst == 0) {
        orow = Cout + (size_t)r * N;
      } else {
        int l = r & 255; int n = r >> 8; int c = n & 31; int b = n >> 5;
        orow = Cout + ((size_t)(b*8192 + l*32 + c)) * 128;
      }
      #pragma unroll
      for (int j=0;j<4;j++){
        int cc = col0 + wn + j*8 + tig*2;
        float2 v = make_float2(acc[i][j][half*2], acc[i][j][half*2+1]);
        *reinterpret_cast<float2*>(orow + cc) = v;
      }
    }
  }
}

// ==================== dual xproj: single-TF32, A+W double-buffered, N=40 ====================
__global__ void __launch_bounds__(256)
xproj_dual_kernel(const float* __restrict__ A0, const float* __restrict__ W0, float* __restrict__ C0g,
                  const float* __restrict__ A1, const float* __restrict__ W1, float* __restrict__ C1g)
{
  const float* A; const float* W; float* Cout;
  if (blockIdx.z == 0) { A=A0; W=W0; Cout=C0g; }
  else                 { A=A1; W=W1; Cout=C1g; }

  const int N = 40, K = 256;
  const int RS = 136, WS = 72;   // strides % 32 == 8 -> conflict-free fragment rows; WS covers padded cols 0..63
  __shared__ uint32_t Ah[2][16*RS];
  __shared__ uint32_t Wh[2][16*WS];

  int tid  = threadIdx.x;
  int row0 = blockIdx.y * 128;
  int lane = tid & 31, warp = tid >> 5;
  int wm = (warp & 3) * 32;       // 4 warps in M
  int wn = (warp >> 2) * 32;      // 2 warps in N
  int g  = lane >> 2, tig = lane & 3;

  int am  = tid >> 1;
  int akq = (tid & 1) * 8;
  const float* arow = A + (size_t)(row0 + am) * K;
  int wk  = tid >> 4;
  int wn4 = (tid & 15) * 4;

  float acc[2][4][4];
  #pragma unroll
  for (int i=0;i<2;i++)
    #pragma unroll
    for (int j=0;j<4;j++)
      #pragma unroll
      for (int q=0;q<4;q++) acc[i][j][q]=0.f;

  float av[8], wv[4];
  // prologue: tile 0
  {
    float4 a0 = *reinterpret_cast<const float4*>(arow + akq);
    float4 a1 = *reinterpret_cast<const float4*>(arow + akq + 4);
    av[0]=a0.x; av[1]=a0.y; av[2]=a0.z; av[3]=a0.w;
    av[4]=a1.x; av[5]=a1.y; av[6]=a1.z; av[7]=a1.w;
    #pragma unroll
    for (int j=0;j<4;j++){
      int col = wn4 + j;
      wv[j] = (col < N) ? W[(size_t)wk*N + col] : 0.f;
    }
    #pragma unroll
    for (int q=0;q<8;q++) Ah[0][(akq+q)*RS + am] = f2tf32(av[q]);
    #pragma unroll
    for (int j=0;j<4;j++)  Wh[0][wk*WS + wn4 + j] = f2tf32(wv[j]);
  }
  __syncthreads();

  #pragma unroll 1
  for (int t=0; t<16; t++) {
    int cur = t & 1;
    if (t+1 < 16) {
      int k0 = (t+1) << 4;
      float4 a0 = *reinterpret_cast<const float4*>(arow + k0 + akq);
      float4 a1 = *reinterpret_cast<const float4*>(arow + k0 + akq + 4);
      av[0]=a0.x; av[1]=a0.y; av[2]=a0.z; av[3]=a0.w;
      av[4]=a1.x; av[5]=a1.y; av[6]=a1.z; av[7]=a1.w;
      #pragma unroll
      for (int j=0;j<4;j++){
        int col = wn4 + j;
        wv[j] = (col < N) ? W[(size_t)(k0+wk)*N + col] : 0.f;
      }
    }
    #pragma unroll
    for (int ks=0; ks<16; ks+=8) {
      uint32_t ah[2][4], bh[4][2];
      #pragma unroll
      for (int i=0;i<2;i++){
        int mr = wm + i*16 + g;
        ah[i][0]=Ah[cur][(ks+tig  )*RS+mr];
        ah[i][1]=Ah[cur][(ks+tig  )*RS+mr+8];
        ah[i][2]=Ah[cur][(ks+tig+4)*RS+mr];
        ah[i][3]=Ah[cur][(ks+tig+4)*RS+mr+8];
      }
      #pragma unroll
      for (int j=0;j<4;j++){
        int nc = wn + j*8 + g;
        bh[j][0]=Wh[cur][(ks+tig  )*WS+nc];
        bh[j][1]=Wh[cur][(ks+tig+4)*WS+nc];
      }
      #pragma unroll
      for (int i=0;i<2;i++)
        #pragma unroll
        for (int j=0;j<4;j++)
          mma_tf32(acc[i][j], ah[i][0],ah[i][1],ah[i][2],ah[i][3], bh[j][0],bh[j][1]);
    }
    if (t+1 < 16) {
      int nxt = (t+1) & 1;
      #pragma unroll
      for (int q=0;q<8;q++) Ah[nxt][(akq+q)*RS + am] = f2tf32(av[q]);
      #pragma unroll
      for (int j=0;j<4;j++)  Wh[nxt][wk*WS + wn4 + j] = f2tf32(wv[j]);
      __syncthreads();
    }
  }

  #pragma unroll
  for (int i=0;i<2;i++){
    int r_lo = row0 + wm + i*16 + g;
    #pragma unroll
    for (int half=0; half<2; half++){
      int r = r_lo + half*8;
      #pragma unroll
      for (int j=0;j<4;j++){
        int cc = wn + j*8 + tig*2;
        if (cc < N) {
          float2 v = make_float2(acc[i][j][half*2], acc[i][j][half*2+1]);
          *reinterpret_cast<float2*>(Cout + (size_t)r*N + cc) = v;
        }
      }
    }
  }
}

// ==================== dual conv: causal depthwise (DC=4) + bias + silu ====================
template<int CLC, int LSEQ>
__device__ __forceinline__ void conv_seq(int blk, const float* __restrict__ xz,
                                         const float* __restrict__ cw, const float* __restrict__ cb,
                                         float* __restrict__ uo, int d)
{
  float w0=cw[d], w1=cw[256+d], w2=cw[512+d], w3=cw[768+d];
  float b = cb[d];
  const float* base = xz + (size_t)blk*CLC*512;
  float* ub = uo + (size_t)blk*CLC*256;
  bool first = ((blk*CLC) % LSEQ) == 0;
  float x0 = first ? 0.f : base[(ptrdiff_t)(-3)*512 + d];
  float x1 = first ? 0.f : base[(ptrdiff_t)(-2)*512 + d];
  float x2 = first ? 0.f : base[(ptrdiff_t)(-1)*512 + d];
  #pragma unroll 4
  for (int l=0;l<CLC;l+=4){
    float xa = base[(size_t)(l+0)*512 + d];
    float xb = base[(size_t)(l+1)*512 + d];
    float xc = base[(size_t)(l+2)*512 + d];
    float xd = base[(size_t)(l+3)*512 + d];
    float va = fmaf(x0,w0, fmaf(x1,w1, fmaf(x2,w2, fmaf(xa,w3, b))));
    float vb = fmaf(x1,w0, fmaf(x2,w1, fmaf(xa,w2, fmaf(xb,w3, b))));
    float vc = fmaf(x2,w0, fmaf(xa,w1, fmaf(xb,w2, fmaf(xc,w3, b))));
    float vd = fmaf(xa,w0, fmaf(xb,w1, fmaf(xc,w2, fmaf(xd,w3, b))));
    ub[(size_t)(l+0)*256 + d] = siluf(va);
    ub[(size_t)(l+1)*256 + d] = siluf(vb);
    ub[(size_t)(l+2)*256 + d] = siluf(vc);
    ub[(size_t)(l+3)*256 + d] = siluf(vd);
    x0=xb; x1=xc; x2=xd;
  }
}

__global__ void conv_dual_kernel(const float* __restrict__ xz_t, const float* __restrict__ cw_t,
                                 const float* __restrict__ cb_t, float* __restrict__ u_t,
                                 const float* __restrict__ xz_c, const float* __restrict__ cw_c,
                                 const float* __restrict__ cb_c, float* __restrict__ u_c)
{
  int d = threadIdx.x;
  if (blockIdx.x < 512) conv_seq<64,256>(blockIdx.x,       xz_t, cw_t, cb_t, u_t, d);
  else                  conv_seq<16,32 >(blockIdx.x - 512, xz_c, cw_c, cb_c, u_c, d);
}

// ==================== ILP scan (shared device body) ====================
template<int CL>
__device__ __forceinline__ void scan_seq(float* __restrict__ sx, int n,
    const float* __restrict__ xdbl, const float* __restrict__ w_dt, const float* __restrict__ b_dt,
    const float* __restrict__ u, const float* __restrict__ a_log,
    const float* __restrict__ dskip, const float* __restrict__ xz, float* __restrict__ gy)
{
  int d = threadIdx.x;
  size_t tbase = (size_t)n * CL;

  for (int i=d; i<CL*40; i+=256) sx[i] = xdbl[tbase*40 + i];

  float w[8];
  #pragma unroll
  for (int r=0;r<8;r++) w[r] = w_dt[r*256 + d];
  float bdt = b_dt[d];
  float A[16]; bool geo = true;
  #pragma unroll
  for (int s=0;s<16;s++){
    A[s] = -__expf(a_log[d*16+s]);
    geo = geo && (fabsf(A[s] + (float)(s+1)) < 1e-4f*(float)(s+1));
  }
  float Dd = dskip[d];
  __syncthreads();

  if (geo) {
    uint64_t h2[8];
    #pragma unroll
    for (int k=0;k<8;k++) h2[k] = pack2(0.f, 0.f);

    #pragma unroll 1
    for (int l0=0; l0<CL; l0+=8){
      float uv[8], gz[8], e1v[8], duv[8];
      #pragma unroll
      for (int j=0;j<8;j++) uv[j] = u[(tbase+l0+j)*256 + d];
      #pragma unroll
      for (int j=0;j<8;j++) gz[j] = xz[(tbase+l0+j)*512 + 256 + d];
      #pragma unroll
      for (int j=0;j<8;j++){
        const float* row = &sx[(l0+j)*40];
        float a0 = fmaf(row[0],w[0], fmaf(row[1],w[1], fmaf(row[2],w[2], fmaf(row[3],w[3], bdt))));
        float a1 = fmaf(row[4],w[4], fmaf(row[5],w[5], fmaf(row[6],w[6], row[7]*w[7])));
        float dtv = softplusf(a0 + a1);
        e1v[j] = __expf(-dtv);
        duv[j] = dtv * uv[j];
        gz[j]  = siluf(gz[j]);
      }
      #pragma unroll
      for (int j=0;j<8;j++){
        const float* row = &sx[(l0+j)*40];
        float e1 = e1v[j];
        float e2 = e1*e1;
        uint64_t e22 = pack2(e2, e2);
        uint64_t p2[8];
        p2[0] = pack2(e1, e2);
        #pragma unroll
        for (int k=1;k<8;k++) p2[k] = mul2(p2[k-1], e22);
        uint64_t du2 = pack2(duv[j], duv[j]);
        uint64_t acca = pack2(0.f,0.f), accb = pack2(0.f,0.f);
        #pragma unroll
        for (int k=0;k<8;k+=2){
          float2 bva = *reinterpret_cast<const float2*>(row + 8  + 2*k);
          float2 cva = *reinterpret_cast<const float2*>(row + 24 + 2*k);
          float2 bvb = *reinterpret_cast<const float2*>(row + 8  + 2*k + 2);
          float2 cvb = *reinterpret_cast<const float2*>(row + 24 + 2*k + 2);
          h2[k]   = fma2(h2[k],   p2[k],   mul2(du2, pack2(bva.x,bva.y)));
          h2[k+1] = fma2(h2[k+1], p2[k+1], mul2(du2, pack2(bvb.x,bvb.y)));
          acca = fma2(h2[k],   pack2(cva.x,cva.y), acca);
          accb = fma2(h2[k+1], pack2(cvb.x,cvb.y), accb);
        }
        float a0,a1,b0,b1;
        unpack2(acca, a0, a1);
        unpack2(accb, b0, b1);
        float acc = (a0+a1)+(b0+b1);
        gy[(tbase+l0+j)*256 + d] = (acc + uv[j]*Dd) * gz[j];
      }
    }
  } else {
    float h[16];
    #pragma unroll
    for (int s=0;s<16;s++) h[s]=0.f;
    for (int l=0; l<CL; l++){
      size_t t = tbase + l;
      const float* row = &sx[l*40];
      float adt = bdt;
      #pragma unroll
      for (int r=0;r<8;r++) adt = fmaf(row[r], w[r], adt);
      float dtv = softplusf(adt);
      float uv = u[t*256 + d];
      float du = dtv * uv;
      float acc = 0.f;
      #pragma unroll
      for (int s=0;s<16;s++){
        float dA = __expf(dtv * A[s]);
        h[s] = fmaf(h[s], dA, du*row[8+s]);
        acc  = fmaf(h[s], row[24+s], acc);
      }
      float zv = xz[t*512 + 256 + d];
      gy[t*256+d] = (acc + uv*Dd) * siluf(zv);
    }
  }
}

__global__ void __launch_bounds__(256)
scan_dual_kernel(const float* __restrict__ xd_t, const float* __restrict__ twdt, const float* __restrict__ tbdt,
                 const float* __restrict__ u_t, const float* __restrict__ talog,
                 const float* __restrict__ td, const float* __restrict__ xz_t, float* __restrict__ gy_t,
                 const float* __restrict__ xd_c, const float* __restrict__ cwdt, const float* __restrict__ cbdt,
                 const float* __restrict__ u_c, const float* __restrict__ calog,
                 const float* __restrict__ cd, const float* __restrict__ xz_c, float* __restrict__ gy_c)
{
  __shared__ float sx[256*40];
  if (blockIdx.x < 128)
    scan_seq<256>(sx, blockIdx.x,       xd_t, twdt, tbdt, u_t, talog, td, xz_t, gy_t);
  else
    scan_seq<32 >(sx, blockIdx.x - 128, xd_c, cwdt, cbdt, u_c, calog, cd, xz_c, gy_c);
}

// ==================== fused mean + Pdiag ====================
__global__ void meanpdiag_kernel(const float* __restrict__ x, const float* __restrict__ gw,
                                 const float* __restrict__ gb, float* __restrict__ Pd){
  int bc = blockIdx.x;      // 128 blocks
  int d  = threadIdx.x;     // 128 threads
  int b = bc >> 5, c = bc & 31;
  const float* base = x + ((size_t)b*8192 + c)*128 + d;
  float s0=0.f, s1=0.f, s2=0.f, s3=0.f;
  #pragma unroll 4
  for (int l=0;l<256;l+=4){
    s0 += base[(size_t)(l+0)*4096];
    s1 += base[(size_t)(l+1)*4096];
    s2 += base[(size_t)(l+2)*4096];
    s3 += base[(size_t)(l+3)*4096];
  }
  __shared__ float sm[128];
  sm[d] = (s0+s1+s2+s3) * (1.f/256.f);
  __syncthreads();
  __shared__ float part[2];
  if (d < 64){
    float acc = gb[d];
    #pragma unroll 8
    for (int dd=0; dd<128; dd++) acc = fmaf(sm[dd], gw[dd*64 + d], acc);
    float sq = acc * acc;
    #pragma unroll
    for (int off=16; off>0; off>>=1) sq += __shfl_down_sync(0xffffffffu, sq, off);
    if ((d & 31) == 0) part[d >> 5] = sq;
  }
  __syncthreads();
  if (d == 0) {
    float ss = part[0] + part[1];
    Pd[bc] = 1.f / (1.f + __expf(-ss * 0.125f));
  }
}

// ==================== launch ====================
extern "C" void kernel_launch(void* const* d_in, const int* in_sizes, int n_in,
                              void* d_out, int out_size)
{
  const float* x        = (const float*)d_in[0];
  const float* t_w_in   = (const float*)d_in[1];
  const float* t_conv_w = (const float*)d_in[2];
  const float* t_conv_b = (const float*)d_in[3];
  const float* t_w_xproj= (const float*)d_in[4];
  const float* t_w_dt   = (const float*)d_in[5];
  const float* t_b_dt   = (const float*)d_in[6];
  const float* t_a_log  = (const float*)d_in[7];
  const float* t_d      = (const float*)d_in[8];
  const float* t_w_out  = (const float*)d_in[9];
  const float* c_w_in   = (const float*)d_in[10];
  const float* c_conv_w = (const float*)d_in[11];
  const float* c_conv_b = (const float*)d_in[12];
  const float* c_w_xproj= (const float*)d_in[13];
  const float* c_w_dt   = (const float*)d_in[14];
  const float* c_b_dt   = (const float*)d_in[15];
  const float* c_a_log  = (const float*)d_in[16];
  const float* c_d      = (const float*)d_in[17];
  const float* c_w_out  = (const float*)d_in[18];
  const float* gw_node  = (const float*)d_in[19];
  const float* gb_node  = (const float*)d_in[20];
  float* out = (float*)d_out;

  float *xz_t, *xz_c, *u_t, *u_c, *xd_t, *xd_c, *gy_t, *gy_c, *Pd;
  cudaGetSymbolAddress((void**)&xz_t, g_xz_t);
  cudaGetSymbolAddress((void**)&xz_c, g_xz_c);
  cudaGetSymbolAddress((void**)&u_t,  g_u_t);
  cudaGetSymbolAddress((void**)&u_c,  g_u_c);
  cudaGetSymbolAddress((void**)&xd_t, g_xd_t);
  cudaGetSymbolAddress((void**)&xd_c, g_xd_c);
  cudaGetSymbolAddress((void**)&gy_t, g_gy_t);
  cudaGetSymbolAddress((void**)&gy_c, g_gy_c);
  cudaGetSymbolAddress((void**)&Pd,   g_Pd);

  // stage 0: channel gates (needed by C-path w_in)
  meanpdiag_kernel<<<128, 128>>>(x, gw_node, gb_node, Pd);

  // stage 1: both w_in GEMMs
  gemm_dual_kernel<<<dim3(4,256,2), 256>>>(x, t_w_in, xz_t, 1, 0,
                                           x, c_w_in, xz_c, 2, 0,
                                           Pd, TOK, 512, 128);
  // stage 2: both convs
  conv_dual_kernel<<<512+2048, 256>>>(xz_t, t_conv_w, t_conv_b, u_t,
                                      xz_c, c_conv_w, c_conv_b, u_c);
  // stage 3: both xprojs
  xproj_dual_kernel<<<dim3(1,256,2), 256>>>(u_t, t_w_xproj, xd_t,
                                            u_c, c_w_xproj, xd_c);
  // stage 4: both scans (C scan hides under T scan)
  scan_dual_kernel<<<128+1024, 256>>>(xd_t, t_w_dt, t_b_dt, u_t, t_a_log, t_d, xz_t, gy_t,
                                      xd_c, c_w_dt, c_b_dt, u_c, c_a_log, c_d, xz_c, gy_c);
  // stage 5: both w_out GEMMs
  gemm_dual_kernel<<<dim3(1,256,2), 256>>>(gy_t, t_w_out, out,                  0, 1,
                                           gy_c, c_w_out, out + (size_t)TOK*128, 0, 0,
                                           Pd, TOK, 128, 256);
}

// round 16
// speedup vs baseline: 1.0091x; 1.0091x over previous
#include <cuda_runtime.h>
#include <math.h>
#include <stdint.h>

#define TOK 32768

// -------------------- scratch (device globals; no allocs) --------------------
__device__ float g_xz_t [(size_t)TOK*512];
__device__ float g_xz_c [(size_t)TOK*512];
__device__ float g_u_t  [(size_t)TOK*256];
__device__ float g_u_c  [(size_t)TOK*256];
__device__ float g_xd_t [(size_t)TOK*40];
__device__ float g_xd_c [(size_t)TOK*40];
__device__ float g_gy_t [(size_t)TOK*256];
__device__ float g_gy_c [(size_t)TOK*256];
__device__ float g_Pd   [4*32];

__device__ __forceinline__ float siluf(float v){ return v / (1.f + __expf(-v)); }
__device__ __forceinline__ float softplusf(float v){
  return (v > 20.f) ? v : __logf(1.f + __expf(v));
}

__device__ __forceinline__ uint32_t f2tf32(float v){
  uint32_t r; asm("cvt.rna.tf32.f32 %0, %1;" : "=r"(r) : "f"(v)); return r;
}
__device__ __forceinline__ void mma_tf32(float* d,
    uint32_t a0,uint32_t a1,uint32_t a2,uint32_t a3,uint32_t b0,uint32_t b1){
  asm volatile("mma.sync.aligned.m16n8k8.row.col.f32.tf32.tf32.f32 "
    "{%0,%1,%2,%3}, {%4,%5,%6,%7}, {%8,%9}, {%0,%1,%2,%3};"
    : "+f"(d[0]),"+f"(d[1]),"+f"(d[2]),"+f"(d[3])
    : "r"(a0),"r"(a1),"r"(a2),"r"(a3),"r"(b0),"r"(b1));
}

// -------------------- packed f32x2 helpers --------------------
__device__ __forceinline__ uint64_t pack2(float lo, float hi){
  uint64_t r; asm("mov.b64 %0, {%1,%2};" : "=l"(r) : "f"(lo), "f"(hi)); return r;
}
__device__ __forceinline__ void unpack2(uint64_t v, float& lo, float& hi){
  asm("mov.b64 {%0,%1}, %2;" : "=f"(lo), "=f"(hi) : "l"(v));
}
__device__ __forceinline__ uint64_t fma2(uint64_t a, uint64_t b, uint64_t c){
  uint64_t d; asm("fma.rn.f32x2 %0, %1, %2, %3;" : "=l"(d) : "l"(a), "l"(b), "l"(c)); return d;
}
__device__ __forceinline__ uint64_t mul2(uint64_t a, uint64_t b){
  uint64_t d; asm("mul.rn.f32x2 %0, %1, %2;" : "=l"(d) : "l"(a), "l"(b)); return d;
}

// ==================== dual tf32 GEMM: both paths in one launch (blockIdx.z) ====================
__global__ void __launch_bounds__(256)
gemm_dual_kernel(const float* __restrict__ A0, const float* __restrict__ W0, float* __restrict__ C0,
                 int asrc0, int cdst0,
                 const float* __restrict__ A1, const float* __restrict__ W1, float* __restrict__ C1,
                 int asrc1, int cdst1,
                 const float* __restrict__ Pd, int M, int N, int K)
{
  const float* A; const float* W; float* Cout; int asrc, cdst;
  if (blockIdx.z == 0) { A=A0; W=W0; Cout=C0; asrc=asrc0; cdst=cdst0; }
  else                 { A=A1; W=W1; Cout=C1; asrc=asrc1; cdst=cdst1; }

  const int RS = 136;
  __shared__ uint32_t As[2][16*RS];
  __shared__ uint32_t Ws[2][16*RS];

  int tid  = threadIdx.x;
  int row0 = blockIdx.y * 128;
  int col0 = blockIdx.x * 128;
  int lane = tid & 31, warp = tid >> 5;
  int wm = (warp & 1) * 64;
  int wn = (warp >> 1) * 32;
  int g  = lane >> 2, tig = lane & 3;

  int am  = tid >> 1;
  int akq = (tid & 1) * 8;
  int ar  = row0 + am;
  const float* arow;
  float ascale = 1.f;
  if (asrc == 0) {
    arow = A + (size_t)ar * K;
  } else if (asrc == 1) {
    int l = ar & 255; int n = ar >> 8; int c = n & 31; int b = n >> 5;
    arow = A + ((size_t)(b*8192 + l*32 + c)) * 128;
  } else {
    arow = A + (size_t)ar * 128;
    ascale = Pd[((ar >> 13) << 5) | (ar & 31)];
  }
  int wk  = tid >> 4;
  int wn8 = (tid & 15) * 8;

  float acc[4][4][4];
  #pragma unroll
  for (int i=0;i<4;i++)
    #pragma unroll
    for (int j=0;j<4;j++)
      #pragma unroll
      for (int q=0;q<4;q++) acc[i][j][q]=0.f;

  float ast[8], wst[8];
  {
    float4 a0 = *reinterpret_cast<const float4*>(arow + akq);
    float4 a1 = *reinterpret_cast<const float4*>(arow + akq + 4);
    ast[0]=a0.x; ast[1]=a0.y; ast[2]=a0.z; ast[3]=a0.w;
    ast[4]=a1.x; ast[5]=a1.y; ast[6]=a1.z; ast[7]=a1.w;
    float4 w0 = *reinterpret_cast<const float4*>(W + (size_t)wk*N + col0 + wn8);
    float4 w1 = *reinterpret_cast<const float4*>(W + (size_t)wk*N + col0 + wn8 + 4);
    wst[0]=w0.x; wst[1]=w0.y; wst[2]=w0.z; wst[3]=w0.w;
    wst[4]=w1.x; wst[5]=w1.y; wst[6]=w1.z; wst[7]=w1.w;
  }
  {
    #pragma unroll
    for (int q=0;q<8;q++) As[0][(akq+q)*RS + am] = f2tf32(ast[q]*ascale);
    #pragma unroll
    for (int q=0;q<8;q++) Ws[0][wk*RS + wn8 + q] = f2tf32(wst[q]);
  }
  __syncthreads();

  int nt = K >> 4;
  for (int t=0; t<nt; t++) {
    int cur = t & 1;
    if (t+1 < nt) {
      int k0 = (t+1) << 4;
      float4 a0 = *reinterpret_cast<const float4*>(arow + k0 + akq);
      float4 a1 = *reinterpret_cast<const float4*>(arow + k0 + akq + 4);
      ast[0]=a0.x; ast[1]=a0.y; ast[2]=a0.z; ast[3]=a0.w;
      ast[4]=a1.x; ast[5]=a1.y; ast[6]=a1.z; ast[7]=a1.w;
      float4 w0 = *reinterpret_cast<const float4*>(W + (size_t)(k0+wk)*N + col0 + wn8);
      float4 w1 = *reinterpret_cast<const float4*>(W + (size_t)(k0+wk)*N + col0 + wn8 + 4);
      wst[0]=w0.x; wst[1]=w0.y; wst[2]=w0.z; wst[3]=w0.w;
      wst[4]=w1.x; wst[5]=w1.y; wst[6]=w1.z; wst[7]=w1.w;
    }
    #pragma unroll
    for (int ks=0; ks<16; ks+=8) {
      uint32_t af[4][4], bf[4][2];
      #pragma unroll
      for (int i=0;i<4;i++){
        int mr = wm + i*16 + g;
        af[i][0] = As[cur][(ks+tig  )*RS + mr];
        af[i][1] = As[cur][(ks+tig  )*RS + mr + 8];
        af[i][2] = As[cur][(ks+tig+4)*RS + mr];
        af[i][3] = As[cur][(ks+tig+4)*RS + mr + 8];
      }
      #pragma unroll
      for (int j=0;j<4;j++){
        int nc = wn + j*8 + g;
        bf[j][0] = Ws[cur][(ks+tig  )*RS + nc];
        bf[j][1] = Ws[cur][(ks+tig+4)*RS + nc];
      }
      #pragma unroll
      for (int i=0;i<4;i++)
        #pragma unroll
        for (int j=0;j<4;j++)
          mma_tf32(acc[i][j], af[i][0],af[i][1],af[i][2],af[i][3], bf[j][0],bf[j][1]);
    }
    if (t+1 < nt) {
      int nxt = (t+1) & 1;
      #pragma unroll
      for (int q=0;q<8;q++) As[nxt][(akq+q)*RS + am] = f2tf32(ast[q]*ascale);
      #pragma unroll
      for (int q=0;q<8;q++) Ws[nxt][wk*RS + wn8 + q] = f2tf32(wst[q]);
      __syncthreads();
    }
  }

  #pragma unroll
  for (int i=0;i<4;i++){
    int r_lo = row0 + wm + i*16 + g;
    #pragma unroll
    for (int half=0; half<2; half++){
      int r = r_lo + half*8;
      float* orow;
      if (cdst == 0) {
        orow = Cout + (size_t)r * N;
      } else {
        int l = r & 255; int n = r >> 8; int c = n & 31; int b = n >> 5;
        orow = Cout + ((size_t)(b*8192 + l*32 + c)) * 128;
      }
      #pragma unroll
      for (int j=0;j<4;j++){
        int cc = col0 + wn + j*8 + tig*2;
        float2 v = make_float2(acc[i][j][half*2], acc[i][j][half*2+1]);
        *reinterpret_cast<float2*>(orow + cc) = v;
      }
    }
  }
}

// ==================== dual xproj GEMM: single-TF32, R13 layout (best measured) ====================
__global__ void __launch_bounds__(256)
xproj_dual_kernel(const float* __restrict__ A0, const float* __restrict__ W0, float* __restrict__ C0g,
                  const float* __restrict__ A1, const float* __restrict__ W1, float* __restrict__ C1g)
{
  const float* A; const float* W; float* Cout;
  if (blockIdx.z == 0) { A=A0; W=W0; Cout=C0g; }
  else                 { A=A1; W=W1; Cout=C1g; }

  const int N = 40, K = 256;
  const int RS = 136, WS = 72;
  __shared__ uint32_t Ah[16*RS];
  __shared__ uint32_t Wh[16*WS];

  int tid  = threadIdx.x;
  int row0 = blockIdx.y * 128;
  int lane = tid & 31, warp = tid >> 5;
  int wm = (warp & 3) * 32;
  int wn = (warp >> 2) * 32;
  int g  = lane >> 2, tig = lane & 3;

  int am  = tid >> 1;
  int akq = (tid & 1) * 8;
  const float* arow = A + (size_t)(row0 + am) * K;
  int wk  = tid >> 4;
  int wn4 = (tid & 15) * 4;

  float acc[2][4][4];
  #pragma unroll
  for (int i=0;i<2;i++)
    #pragma unroll
    for (int j=0;j<4;j++)
      #pragma unroll
      for (int q=0;q<4;q++) acc[i][j][q]=0.f;

  for (int k0=0; k0<K; k0+=16) {
    float av[8], wv[4];
    float4 a0 = *reinterpret_cast<const float4*>(arow + k0 + akq);
    float4 a1 = *reinterpret_cast<const float4*>(arow + k0 + akq + 4);
    av[0]=a0.x; av[1]=a0.y; av[2]=a0.z; av[3]=a0.w;
    av[4]=a1.x; av[5]=a1.y; av[6]=a1.z; av[7]=a1.w;
    #pragma unroll
    for (int j=0;j<4;j++){
      int col = wn4 + j;
      wv[j] = (col < N) ? W[(size_t)(k0+wk)*N + col] : 0.f;
    }
    __syncthreads();
    #pragma unroll
    for (int q=0;q<8;q++)
      Ah[(akq+q)*RS + am] = f2tf32(av[q]);
    #pragma unroll
    for (int j=0;j<4;j++)
      Wh[wk*WS + wn4 + j] = f2tf32(wv[j]);
    __syncthreads();
    #pragma unroll
    for (int ks=0; ks<16; ks+=8) {
      uint32_t ah[2][4], bh[4][2];
      #pragma unroll
      for (int i=0;i<2;i++){
        int mr = wm + i*16 + g;
        ah[i][0]=Ah[(ks+tig  )*RS+mr];
        ah[i][1]=Ah[(ks+tig  )*RS+mr+8];
        ah[i][2]=Ah[(ks+tig+4)*RS+mr];
        ah[i][3]=Ah[(ks+tig+4)*RS+mr+8];
      }
      #pragma unroll
      for (int j=0;j<4;j++){
        int nc = wn + j*8 + g;
        bh[j][0]=Wh[(ks+tig  )*WS+nc];
        bh[j][1]=Wh[(ks+tig+4)*WS+nc];
      }
      #pragma unroll
      for (int i=0;i<2;i++)
        #pragma unroll
        for (int j=0;j<4;j++)
          mma_tf32(acc[i][j], ah[i][0],ah[i][1],ah[i][2],ah[i][3], bh[j][0],bh[j][1]);
    }
  }

  #pragma unroll
  for (int i=0;i<2;i++){
    int r_lo = row0 + wm + i*16 + g;
    #pragma unroll
    for (int half=0; half<2; half++){
      int r = r_lo + half*8;
      #pragma unroll
      for (int j=0;j<4;j++){
        int cc = wn + j*8 + tig*2;
        if (cc < N) {
          float2 v = make_float2(acc[i][j][half*2], acc[i][j][half*2+1]);
          *reinterpret_cast<float2*>(Cout + (size_t)r*N + cc) = v;
        }
      }
    }
  }
}

// ==================== dual conv: causal depthwise (DC=4) + bias + silu ====================
template<int CLC, int LSEQ>
__device__ __forceinline__ void conv_seq(int blk, const float* __restrict__ xz,
                                         const float* __restrict__ cw, const float* __restrict__ cb,
                                         float* __restrict__ uo, int d)
{
  float w0=cw[d], w1=cw[256+d], w2=cw[512+d], w3=cw[768+d];
  float b = cb[d];
  const float* base = xz + (size_t)blk*CLC*512;
  float* ub = uo + (size_t)blk*CLC*256;
  bool first = ((blk*CLC) % LSEQ) == 0;
  float x0 = first ? 0.f : base[(ptrdiff_t)(-3)*512 + d];
  float x1 = first ? 0.f : base[(ptrdiff_t)(-2)*512 + d];
  float x2 = first ? 0.f : base[(ptrdiff_t)(-1)*512 + d];
  #pragma unroll 4
  for (int l=0;l<CLC;l+=4){
    float xa = base[(size_t)(l+0)*512 + d];
    float xb = base[(size_t)(l+1)*512 + d];
    float xc = base[(size_t)(l+2)*512 + d];
    float xd = base[(size_t)(l+3)*512 + d];
    float va = fmaf(x0,w0, fmaf(x1,w1, fmaf(x2,w2, fmaf(xa,w3, b))));
    float vb = fmaf(x1,w0, fmaf(x2,w1, fmaf(xa,w2, fmaf(xb,w3, b))));
    float vc = fmaf(x2,w0, fmaf(xa,w1, fmaf(xb,w2, fmaf(xc,w3, b))));
    float vd = fmaf(xa,w0, fmaf(xb,w1, fmaf(xc,w2, fmaf(xd,w3, b))));
    ub[(size_t)(l+0)*256 + d] = siluf(va);
    ub[(size_t)(l+1)*256 + d] = siluf(vb);
    ub[(size_t)(l+2)*256 + d] = siluf(vc);
    ub[(size_t)(l+3)*256 + d] = siluf(vd);
    x0=xb; x1=xc; x2=xd;
  }
}

__global__ void conv_dual_kernel(const float* __restrict__ xz_t, const float* __restrict__ cw_t,
                                 const float* __restrict__ cb_t, float* __restrict__ u_t,
                                 const float* __restrict__ xz_c, const float* __restrict__ cw_c,
                                 const float* __restrict__ cb_c, float* __restrict__ u_c)
{
  int d = threadIdx.x;
  if (blockIdx.x < 512) conv_seq<64,256>(blockIdx.x,       xz_t, cw_t, cb_t, u_t, d);
  else                  conv_seq<16,32 >(blockIdx.x - 512, xz_c, cw_c, cb_c, u_c, d);
}

// ==================== ILP scan with software-pipelined tile loads ====================
// one 8-step tile: phase1 (batched transcendentals) + phase2 (serial f32x2 FMA)
#define SCAN_TILE(UV, GZ, L0) do {                                              \
  float e1v[8], duv[8];                                                         \
  _Pragma("unroll")                                                             \
  for (int j=0;j<8;j++){                                                        \
    const float* row = &sx[((L0)+j)*40];                                        \
    float a0_ = fmaf(row[0],w[0], fmaf(row[1],w[1], fmaf(row[2],w[2], fmaf(row[3],w[3], bdt)))); \
    float a1_ = fmaf(row[4],w[4], fmaf(row[5],w[5], fmaf(row[6],w[6], row[7]*w[7])));            \
    float dtv = softplusf(a0_ + a1_);                                           \
    e1v[j] = __expf(-dtv);                                                      \
    duv[j] = dtv * UV[j];                                                       \
    GZ[j]  = siluf(GZ[j]);                                                      \
  }                                                                             \
  _Pragma("unroll")                                                             \
  for (int j=0;j<8;j++){                                                        \
    const float* row = &sx[((L0)+j)*40];                                        \
    float e1 = e1v[j];                                                          \
    float e2 = e1*e1;                                                           \
    uint64_t e22 = pack2(e2, e2);                                               \
    uint64_t p2[8];                                                             \
    p2[0] = pack2(e1, e2);                                                      \
    _Pragma("unroll")                                                           \
    for (int k=1;k<8;k++) p2[k] = mul2(p2[k-1], e22);                           \
    uint64_t du2 = pack2(duv[j], duv[j]);                                       \
    uint64_t acca = pack2(0.f,0.f), accb = pack2(0.f,0.f);                      \
    _Pragma("unroll")                                                           \
    for (int k=0;k<8;k+=2){                                                     \
      float2 bva = *reinterpret_cast<const float2*>(row + 8  + 2*k);            \
      float2 cva = *reinterpret_cast<const float2*>(row + 24 + 2*k);            \
      float2 bvb = *reinterpret_cast<const float2*>(row + 8  + 2*k + 2);        \
      float2 cvb = *reinterpret_cast<const float2*>(row + 24 + 2*k + 2);        \
      h2[k]   = fma2(h2[k],   p2[k],   mul2(du2, pack2(bva.x,bva.y)));          \
      h2[k+1] = fma2(h2[k+1], p2[k+1], mul2(du2, pack2(bvb.x,bvb.y)));          \
      acca = fma2(h2[k],   pack2(cva.x,cva.y), acca);                           \
      accb = fma2(h2[k+1], pack2(cvb.x,cvb.y), accb);                           \
    }                                                                           \
    float r0,r1,r2,r3;                                                          \
    unpack2(acca, r0, r1);                                                      \
    unpack2(accb, r2, r3);                                                      \
    float acc = (r0+r1)+(r2+r3);                                                \
    gy[(tbase+(L0)+j)*256 + d] = (acc + UV[j]*Dd) * GZ[j];                      \
  }                                                                             \
} while(0)

template<int CL>
__device__ __forceinline__ void scan_seq(float* __restrict__ sx, int n,
    const float* __restrict__ xdbl, const float* __restrict__ w_dt, const float* __restrict__ b_dt,
    const float* __restrict__ u, const float* __restrict__ a_log,
    const float* __restrict__ dskip, const float* __restrict__ xz, float* __restrict__ gy)
{
  int d = threadIdx.x;
  size_t tbase = (size_t)n * CL;

  for (int i=d; i<CL*40; i+=256) sx[i] = xdbl[tbase*40 + i];

  float w[8];
  #pragma unroll
  for (int r=0;r<8;r++) w[r] = w_dt[r*256 + d];
  float bdt = b_dt[d];
  float A[16]; bool geo = true;
  #pragma unroll
  for (int s=0;s<16;s++){
    A[s] = -__expf(a_log[d*16+s]);
    geo = geo && (fabsf(A[s] + (float)(s+1)) < 1e-4f*(float)(s+1));
  }
  float Dd = dskip[d];
  __syncthreads();

  if (geo) {
    uint64_t h2[8];
    #pragma unroll
    for (int k=0;k<8;k++) h2[k] = pack2(0.f, 0.f);

    float uvA[8], gzA[8], uvB[8], gzB[8];
    #pragma unroll
    for (int j=0;j<8;j++){
      uvA[j] = u [(tbase+j)*256 + d];
      gzA[j] = xz[(tbase+j)*512 + 256 + d];
    }
    // 2-tile unrolled pipeline: prefetch next tile's u/z before the serial phase
    #pragma unroll 1
    for (int l0=0; l0<CL; l0+=16){
      if (l0+8 < CL) {
        #pragma unroll
        for (int j=0;j<8;j++){
          uvB[j] = u [(tbase+l0+8+j)*256 + d];
          gzB[j] = xz[(tbase+l0+8+j)*512 + 256 + d];
        }
      }
      SCAN_TILE(uvA, gzA, l0);
      if (l0+16 < CL) {
        #pragma unroll
        for (int j=0;j<8;j++){
          uvA[j] = u [(tbase+l0+16+j)*256 + d];
          gzA[j] = xz[(tbase+l0+16+j)*512 + 256 + d];
        }
      }
      SCAN_TILE(uvB, gzB, l0+8);
    }
  } else {
    float h[16];
    #pragma unroll
    for (int s=0;s<16;s++) h[s]=0.f;
    for (int l=0; l<CL; l++){
      size_t t = tbase + l;
      const float* row = &sx[l*40];
      float adt = bdt;
      #pragma unroll
      for (int r=0;r<8;r++) adt = fmaf(row[r], w[r], adt);
      float dtv = softplusf(adt);
      float uv = u[t*256 + d];
      float du = dtv * uv;
      float acc = 0.f;
      #pragma unroll
      for (int s=0;s<16;s++){
        float dA = __expf(dtv * A[s]);
        h[s] = fmaf(h[s], dA, du*row[8+s]);
        acc  = fmaf(h[s], row[24+s], acc);
      }
      float zv = xz[t*512 + 256 + d];
      gy[t*256+d] = (acc + uv*Dd) * siluf(zv);
    }
  }
}

__global__ void __launch_bounds__(256, 2)
scan_dual_kernel(const float* __restrict__ xd_t, const float* __restrict__ twdt, const float* __restrict__ tbdt,
                 const float* __restrict__ u_t, const float* __restrict__ talog,
                 const float* __restrict__ td, const float* __restrict__ xz_t, float* __restrict__ gy_t,
                 const float* __restrict__ xd_c, const float* __restrict__ cwdt, const float* __restrict__ cbdt,
                 const float* __restrict__ u_c, const float* __restrict__ calog,
                 const float* __restrict__ cd, const float* __restrict__ xz_c, float* __restrict__ gy_c)
{
  __shared__ float sx[256*40];
  if (blockIdx.x < 128)
    scan_seq<256>(sx, blockIdx.x,       xd_t, twdt, tbdt, u_t, talog, td, xz_t, gy_t);
  else
    scan_seq<32 >(sx, blockIdx.x - 128, xd_c, cwdt, cbdt, u_c, calog, cd, xz_c, gy_c);
}

// ==================== fused mean + Pdiag ====================
__global__ void meanpdiag_kernel(const float* __restrict__ x, const float* __restrict__ gw,
                                 const float* __restrict__ gb, float* __restrict__ Pd){
  int bc = blockIdx.x;      // 128 blocks
  int d  = threadIdx.x;     // 128 threads
  int b = bc >> 5, c = bc & 31;
  const float* base = x + ((size_t)b*8192 + c)*128 + d;
  float s0=0.f, s1=0.f, s2=0.f, s3=0.f;
  #pragma unroll 4
  for (int l=0;l<256;l+=4){
    s0 += base[(size_t)(l+0)*4096];
    s1 += base[(size_t)(l+1)*4096];
    s2 += base[(size_t)(l+2)*4096];
    s3 += base[(size_t)(l+3)*4096];
  }
  __shared__ float sm[128];
  sm[d] = (s0+s1+s2+s3) * (1.f/256.f);
  __syncthreads();
  __shared__ float part[2];
  if (d < 64){
    float acc = gb[d];
    #pragma unroll 8
    for (int dd=0; dd<128; dd++) acc = fmaf(sm[dd], gw[dd*64 + d], acc);
    float sq = acc * acc;
    #pragma unroll
    for (int off=16; off>0; off>>=1) sq += __shfl_down_sync(0xffffffffu, sq, off);
    if ((d & 31) == 0) part[d >> 5] = sq;
  }
  __syncthreads();
  if (d == 0) {
    float ss = part[0] + part[1];
    Pd[bc] = 1.f / (1.f + __expf(-ss * 0.125f));
  }
}

// ==================== launch ====================
extern "C" void kernel_launch(void* const* d_in, const int* in_sizes, int n_in,
                              void* d_out, int out_size)
{
  const float* x        = (const float*)d_in[0];
  const float* t_w_in   = (const float*)d_in[1];
  const float* t_conv_w = (const float*)d_in[2];
  const float* t_conv_b = (const float*)d_in[3];
  const float* t_w_xproj= (const float*)d_in[4];
  const float* t_w_dt   = (const float*)d_in[5];
  const float* t_b_dt   = (const float*)d_in[6];
  const float* t_a_log  = (const float*)d_in[7];
  const float* t_d      = (const float*)d_in[8];
  const float* t_w_out  = (const float*)d_in[9];
  const float* c_w_in   = (const float*)d_in[10];
  const float* c_conv_w = (const float*)d_in[11];
  const float* c_conv_b = (const float*)d_in[12];
  const float* c_w_xproj= (const float*)d_in[13];
  const float* c_w_dt   = (const float*)d_in[14];
  const float* c_b_dt   = (const float*)d_in[15];
  const float* c_a_log  = (const float*)d_in[16];
  const float* c_d      = (const float*)d_in[17];
  const float* c_w_out  = (const float*)d_in[18];
  const float* gw_node  = (const float*)d_in[19];
  const float* gb_node  = (const float*)d_in[20];
  float* out = (float*)d_out;

  float *xz_t, *xz_c, *u_t, *u_c, *xd_t, *xd_c, *gy_t, *gy_c, *Pd;
  cudaGetSymbolAddress((void**)&xz_t, g_xz_t);
  cudaGetSymbolAddress((void**)&xz_c, g_xz_c);
  cudaGetSymbolAddress((void**)&u_t,  g_u_t);
  cudaGetSymbolAddress((void**)&u_c,  g_u_c);
  cudaGetSymbolAddress((void**)&xd_t, g_xd_t);
  cudaGetSymbolAddress((void**)&xd_c, g_xd_c);
  cudaGetSymbolAddress((void**)&gy_t, g_gy_t);
  cudaGetSymbolAddress((void**)&gy_c, g_gy_c);
  cudaGetSymbolAddress((void**)&Pd,   g_Pd);

  // stage 0: channel gates (needed by C-path w_in)
  meanpdiag_kernel<<<128, 128>>>(x, gw_node, gb_node, Pd);

  // stage 1: both w_in GEMMs
  gemm_dual_kernel<<<dim3(4,256,2), 256>>>(x, t_w_in, xz_t, 1, 0,
                                           x, c_w_in, xz_c, 2, 0,
                                           Pd, TOK, 512, 128);
  // stage 2: both convs
  conv_dual_kernel<<<512+2048, 256>>>(xz_t, t_conv_w, t_conv_b, u_t,
                                      xz_c, c_conv_w, c_conv_b, u_c);
  // stage 3: both xprojs
  xproj_dual_kernel<<<dim3(1,256,2), 256>>>(u_t, t_w_xproj, xd_t,
                                            u_c, c_w_xproj, xd_c);
  // stage 4: both scans (C scan hides under T scan)
  scan_dual_kernel<<<128+1024, 256>>>(xd_t, t_w_dt, t_b_dt, u_t, t_a_log, t_d, xz_t, gy_t,
                                      xd_c, c_w_dt, c_b_dt, u_c, c_a_log, c_d, xz_c, gy_c);
  // stage 5: both w_out GEMMs
  gemm_dual_kernel<<<dim3(1,256,2), 256>>>(gy_t, t_w_out, out,                  0, 1,
                                           gy_c, c_w_out, out + (size_t)TOK*128, 0, 0,
                                           Pd, TOK, 128, 256);
}